// round 12
// baseline (speedup 1.0000x reference)
#include <cuda_runtime.h>
#include <math.h>

#define N_NODES 100000
#define HDIM 64
#define NPB  128
#define TPB  256
#define PAD  32
#define OVF_CAP 65536

// smem layout (float indices)
#define O_CNT 0        // 256
#define O_B   256      // 784  (u0|u1|bih|bhh|bout)
#define O_X   1040     // 128*68 = 8704   (S0/S1/feat/h tile, stride 68)
#define O_W   9744     // 64*200 = 12800  (weights k-major, stride 200)
#define O_GH  22544    // 128*200 = 25600 (gh staging, stride 200)
#define SMEM_FLOATS 48144
#define XS 68
#define NS 200

__device__ int   g_cnt[2 * N_NODES];
__device__ int   g_slots[(size_t)2 * N_NODES * PAD];
__device__ int   g_et_is_i32;
__device__ int   g_ovf_n;
__device__ int2  g_ovf[OVF_CAP];
__device__ float g_C0[192 * 64];
__device__ float g_C1[192 * 64];
__device__ float g_u0[192];
__device__ float g_u1[192];

__device__ __forceinline__ unsigned tf32c(float x)
{
    unsigned r; asm("cvt.rna.tf32.f32 %0, %1;" : "=r"(r) : "f"(x)); return r;
}
__device__ __forceinline__ float tanh_fast(float x)
{
    float t; asm("tanh.approx.f32 %0, %1;" : "=f"(t) : "f"(x)); return t;
}
__device__ __forceinline__ float sigmoid_fast(float x)
{
    return 0.5f * tanh_fast(0.5f * x) + 0.5f;
}
#define MMA(d, a0, a1, a2, a3, b0, b1) \
    asm volatile("mma.sync.aligned.m16n8k8.row.col.f32.tf32.tf32.f32 " \
        "{%0,%1,%2,%3},{%4,%5,%6,%7},{%8,%9},{%0,%1,%2,%3};" \
        : "+f"((d)[0]), "+f"((d)[1]), "+f"((d)[2]), "+f"((d)[3]) \
        : "r"(a0), "r"(a1), "r"(a2), "r"(a3), "r"(b0), "r"(b1))

// =====================================================================
__global__ void detect_et_kernel(const unsigned char* __restrict__ et, int E)
{
    __shared__ int cnt;
    if (threadIdx.x == 0) { cnt = 0; g_ovf_n = 0; }
    __syncthreads();
    int K = 4096 < E ? 4096 : E;
    int local = 0;
    for (int i = threadIdx.x; i < K; i += blockDim.x) local += (et[i] != 0);
    atomicAdd(&cnt, local);
    __syncthreads();
    if (threadIdx.x == 0) g_et_is_i32 = (cnt < K / 4) ? 1 : 0;
}

__global__ void __launch_bounds__(256) place_kernel(
    const int* __restrict__ src, const int* __restrict__ dst,
    const void* __restrict__ et, int E)
{
    int e = blockIdx.x * blockDim.x + threadIdx.x;
    if (e >= E) return;
    bool t;
    if (g_et_is_i32) t = __ldg((const int*)et + e) != 0;
    else             t = __ldg((const unsigned char*)et + e) != 0;
    int ti = t ? 0 : 1;
    int d = __ldg(dst + e), s = __ldg(src + e);
    int seg = d * 2 + ti;
    int slot = atomicAdd(&g_cnt[seg], 1);
    if (slot < PAD) g_slots[(size_t)seg * PAD + slot] = s;
    else {
        int w = atomicAdd(&g_ovf_n, 1);
        if (w < OVF_CAP) g_ovf[w] = make_int2(seg, s);
    }
}

// C0 = Wih@W0, C1 = Wih@W1, u0 = Wih@b0, u1 = Wih@b1
__global__ void compose_kernel(const float* __restrict__ Wih,
                               const float* __restrict__ W0, const float* __restrict__ W1,
                               const float* __restrict__ b0, const float* __restrict__ b1)
{
    int idx = blockIdx.x * blockDim.x + threadIdx.x;
    if (idx < 192 * 64) {
        int r = idx >> 6, k = idx & 63;
        const float* wr = Wih + r * 64;
        float a0 = 0.f, a1 = 0.f;
        #pragma unroll 8
        for (int j = 0; j < 64; j++) {
            float w = __ldg(wr + j);
            a0 += w * __ldg(W0 + j * 64 + k);
            a1 += w * __ldg(W1 + j * 64 + k);
        }
        g_C0[idx] = a0; g_C1[idx] = a1;
    }
    if (idx < 192) {
        const float* wr = Wih + idx * 64;
        float s0 = 0.f, s1 = 0.f;
        #pragma unroll 8
        for (int j = 0; j < 64; j++) {
            float w = __ldg(wr + j);
            s0 += w * __ldg(b0 + j);
            s1 += w * __ldg(b1 + j);
        }
        g_u0[idx] = s0; g_u1[idx] = s1;
    }
}

// =====================================================================
__device__ __forceinline__ void stage_w192(float* sW, const float* __restrict__ W, int tid)
{
    // sW[k*NS + n] = tf32(W[n*64 + k]),  W is [192,64]
    for (int i = tid; i < 192 * 64; i += TPB) {
        int n = i >> 6, k = i & 63;
        sW[k * NS + n] = __uint_as_float(tf32c(__ldg(W + i)));
    }
}

__device__ __forceinline__ void gather_seg(float* sX, const float4* __restrict__ F,
                                           int n0, int ti, int Nn, int tid)
{
    int ovn = g_ovf_n; if (ovn > OVF_CAP) ovn = OVF_CAP;
    #pragma unroll
    for (int it = 0; it < 8; it++) {
        int idx = tid + it * TPB;
        int r = idx >> 4, l = idx & 15;
        int nn = n0 + r;
        float4 acc = make_float4(0.f, 0.f, 0.f, 0.f);
        if (nn < Nn) {
            int seg = nn * 2 + ti;
            int c = g_cnt[seg];
            int m = c < PAD ? c : PAD;
            const int* sl = g_slots + (size_t)seg * PAD;
            int q = 0;
            for (; q + 4 <= m; q += 4) {
                int4 s4 = *(const int4*)(sl + q);
                float4 a = __ldg(F + (size_t)s4.x * 16 + l);
                float4 b = __ldg(F + (size_t)s4.y * 16 + l);
                float4 c2 = __ldg(F + (size_t)s4.z * 16 + l);
                float4 e = __ldg(F + (size_t)s4.w * 16 + l);
                acc.x += (a.x + b.x) + (c2.x + e.x);
                acc.y += (a.y + b.y) + (c2.y + e.y);
                acc.z += (a.z + b.z) + (c2.z + e.z);
                acc.w += (a.w + b.w) + (c2.w + e.w);
            }
            for (; q < m; q++) {
                float4 a = __ldg(F + (size_t)sl[q] * 16 + l);
                acc.x += a.x; acc.y += a.y; acc.z += a.z; acc.w += a.w;
            }
            for (int o = 0; o < ovn; o++) {
                int2 ov = g_ovf[o];
                if (ov.x == seg) {
                    float4 v = __ldg(F + (size_t)ov.y * 16 + l);
                    acc.x += v.x; acc.y += v.y; acc.z += v.z; acc.w += v.w;
                }
            }
        }
        *(uint4*)(sX + r * XS + l * 4) =
            make_uint4(tf32c(acc.x), tf32c(acc.y), tf32c(acc.z), tf32c(acc.w));
    }
}

// one GEMM pass: D[96] += Xtile(this warp's 16 rows) @ Wtile^T (192 cols)
__device__ __forceinline__ void gemm_pass(float* D, const float* sX, const float* sW,
                                          int rA, int tid4, int gid)
{
    #pragma unroll
    for (int kt = 0; kt < 8; kt++) {
        const float* ax = sX + rA * XS + kt * 8 + tid4;
        unsigned a0 = __float_as_uint(ax[0]);
        unsigned a1 = __float_as_uint(ax[8 * XS]);
        unsigned a2 = __float_as_uint(ax[4]);
        unsigned a3 = __float_as_uint(ax[8 * XS + 4]);
        const float* bx = sW + (kt * 8 + tid4) * NS + gid;
        #pragma unroll
        for (int nt = 0; nt < 24; nt++) {
            unsigned b0 = __float_as_uint(bx[nt * 8]);
            unsigned b1 = __float_as_uint(bx[4 * NS + nt * 8]);
            MMA(D + nt * 4, a0, a1, a2, a3, b0, b1);
        }
    }
}

__global__ void __launch_bounds__(TPB, 1) node_kernel(
    const float* __restrict__ feat,
    const float* __restrict__ Whh, const float* __restrict__ Wout,
    const float* __restrict__ bih, const float* __restrict__ bhh,
    const float* __restrict__ bout,
    float* __restrict__ out, int Nn)
{
    extern __shared__ __align__(16) float sm[];
    float* sCnt = sm + O_CNT;
    float* sB   = sm + O_B;
    float* sX   = sm + O_X;
    float* sW   = sm + O_W;
    float* sGH  = sm + O_GH;

    const int tid  = threadIdx.x;
    const int wid  = tid >> 5;
    const int lane = tid & 31;
    const int gid  = lane >> 2;
    const int tid4 = lane & 3;
    const int rA   = wid * 16 + gid;     // this thread's top row (node in tile)
    const int n0   = blockIdx.x * NPB;
    const float4* F = (const float4*)feat;

    for (int i = tid; i < 784; i += TPB) {
        float v;
        if (i < 192)      v = g_u0[i];
        else if (i < 384) v = g_u1[i - 192];
        else if (i < 576) v = __ldg(bih + i - 384);
        else if (i < 768) v = __ldg(bhh + i - 576);
        else              v = __ldg(bout + i - 768);
        sB[i] = v;
    }
    for (int i = tid; i < 256; i += TPB) {
        int m = i & 127, t = i >> 7;
        int nn = n0 + m;
        sCnt[t * 128 + m] = (nn < Nn) ? (float)g_cnt[nn * 2 + t] : 0.f;
    }
    // feat tile (tf32)
    for (int i = tid; i < NPB * 16; i += TPB) {
        int r = i >> 4, l = i & 15;
        int nn = n0 + r;
        float4 v = (nn < Nn) ? __ldg(F + (size_t)nn * 16 + l) : make_float4(0.f, 0.f, 0.f, 0.f);
        *(uint4*)(sX + r * XS + l * 4) = make_uint4(tf32c(v.x), tf32c(v.y), tf32c(v.z), tf32c(v.w));
    }
    stage_w192(sW, Whh, tid);
    __syncthreads();

    // ---- gh = feat @ Whh^T -> sGH ----
    {
        float D[96];
        #pragma unroll
        for (int q = 0; q < 96; q++) D[q] = 0.f;
        gemm_pass(D, sX, sW, rA, tid4, gid);
        #pragma unroll
        for (int nt = 0; nt < 24; nt++) {
            *(float2*)(sGH + rA * NS + nt * 8 + tid4 * 2)       = make_float2(D[nt*4],   D[nt*4+1]);
            *(float2*)(sGH + (rA + 8) * NS + nt * 8 + tid4 * 2) = make_float2(D[nt*4+2], D[nt*4+3]);
        }
    }
    __syncthreads();

    // ---- gi = S0@C0^T + S1@C1^T (accumulated in regs across gathers) ----
    float D[96];
    #pragma unroll
    for (int q = 0; q < 96; q++) D[q] = 0.f;

    gather_seg(sX, F, n0, 0, Nn, tid);
    stage_w192(sW, g_C0, tid);
    __syncthreads();
    gemm_pass(D, sX, sW, rA, tid4, gid);
    __syncthreads();

    gather_seg(sX, F, n0, 1, Nn, tid);
    stage_w192(sW, g_C1, tid);
    __syncthreads();
    gemm_pass(D, sX, sW, rA, tid4, gid);

    // ---- elementwise GRU (fp32); h -> sX (fp32, own rows only) ----
    #pragma unroll
    for (int j = 0; j < 2; j++) {
        const int row = rA + j * 8;
        const float c0m = sCnt[row], c1m = sCnt[128 + row];
        const int valid = (n0 + row) < Nn;
        #pragma unroll
        for (int nt = 0; nt < 8; nt++) {
            float2 fv = make_float2(0.f, 0.f);
            if (valid)
                fv = *(const float2*)(feat + (size_t)(n0 + row) * 64 + nt * 8 + tid4 * 2);
            #pragma unroll
            for (int e = 0; e < 2; e++) {
                int c = nt * 8 + tid4 * 2 + e;
                float gi_r = D[nt * 4 + j * 2 + e];
                float gi_z = D[(8 + nt) * 4 + j * 2 + e];
                float gi_n = D[(16 + nt) * 4 + j * 2 + e];
                float gh_r = sGH[row * NS + c];
                float gh_z = sGH[row * NS + 64 + c];
                float gh_n = sGH[row * NS + 128 + c];
                float gr = gi_r + c0m * sB[c]       + c1m * sB[192 + c] + sB[384 + c] + gh_r + sB[576 + c];
                float gz = gi_z + c0m * sB[64 + c]  + c1m * sB[256 + c] + sB[448 + c] + gh_z + sB[640 + c];
                float gn = gi_n + c0m * sB[128 + c] + c1m * sB[320 + c] + sB[512 + c];
                float hn = gh_n + sB[704 + c];
                float rr = sigmoid_fast(gr);
                float zz = sigmoid_fast(gz);
                float nn = tanh_fast(gn + rr * hn);
                float f  = (e == 0) ? fv.x : fv.y;
                sX[row * XS + c] = nn + zz * (f - nn);
            }
        }
    }
    __syncthreads();

    // ---- classifier (scalar fp32): out = h @ Wout^T + bout ----
    for (int i = tid; i < 1024; i += TPB) {
        int c = i >> 6, k = i & 63;
        sW[k * 16 + c] = __ldg(Wout + i);
    }
    __syncthreads();
    {
        int r  = tid >> 1;
        int cb = (tid & 1) * 8;
        float o[8];
        #pragma unroll
        for (int c = 0; c < 8; c++) o[c] = sB[768 + cb + c];
        #pragma unroll 4
        for (int k = 0; k < 64; k++) {
            float hv = sX[r * XS + k];
            float4 w0 = *(const float4*)(sW + k * 16 + cb);
            float4 w1 = *(const float4*)(sW + k * 16 + cb + 4);
            o[0] += hv * w0.x; o[1] += hv * w0.y; o[2] += hv * w0.z; o[3] += hv * w0.w;
            o[4] += hv * w1.x; o[5] += hv * w1.y; o[6] += hv * w1.z; o[7] += hv * w1.w;
        }
        if (n0 + r < Nn) {
            float4* po = (float4*)(out + (size_t)(n0 + r) * 16 + cb);
            po[0] = make_float4(o[0], o[1], o[2], o[3]);
            po[1] = make_float4(o[4], o[5], o[6], o[7]);
        }
    }
}

// =====================================================================
extern "C" void kernel_launch(void* const* d_in, const int* in_sizes, int n_in,
                              void* d_out, int out_size)
{
    const float* feat = (const float*)d_in[0];
    const int*   src  = (const int*)d_in[1];
    const int*   dst  = (const int*)d_in[2];
    const void*  et   = d_in[3];
    const float* W0   = (const float*)d_in[4];
    const float* b0   = (const float*)d_in[5];
    const float* W1   = (const float*)d_in[6];
    const float* b1   = (const float*)d_in[7];
    const float* Wih  = (const float*)d_in[8];
    const float* Whh  = (const float*)d_in[9];
    const float* bih  = (const float*)d_in[10];
    const float* bhh  = (const float*)d_in[11];
    const float* Wout = (const float*)d_in[12];
    const float* bout = (const float*)d_in[13];
    float* out = (float*)d_out;

    const int E  = in_sizes[1];
    const int Nn = in_sizes[0] / HDIM;

    void* p;
    cudaGetSymbolAddress(&p, g_cnt);
    cudaMemsetAsync(p, 0, sizeof(int) * 2 * N_NODES);

    detect_et_kernel<<<1, 256>>>((const unsigned char*)et, E);
    place_kernel<<<(E + 255) / 256, 256>>>(src, dst, et, E);
    compose_kernel<<<48, 256>>>(Wih, W0, W1, b0, b1);

    size_t smem = SMEM_FLOATS * sizeof(float);   // 192576 B
    cudaFuncSetAttribute(node_kernel, cudaFuncAttributeMaxDynamicSharedMemorySize, (int)smem);
    int nb = (Nn + NPB - 1) / NPB;
    node_kernel<<<nb, TPB, smem>>>(feat, Whh, Wout, bih, bhh, bout, out, Nn);
}

// round 13
// speedup vs baseline: 1.0123x; 1.0123x over previous
#include <cuda_runtime.h>
#include <math.h>

#define N_NODES 100000
#define HDIM 64
#define NPB  128
#define TPB  256
#define PAD  32
#define OVF_CAP 65536

// smem layout (float indices)
#define O_CNT 0        // 256
#define O_B   256      // 784  (u0|u1|bih|bhh|bout)
#define O_F   1040     // 128*68 feat tile (later h)
#define O_S0  9744     // 128*68 S0
#define O_S1  18448    // 128*68 S1
#define O_W   27152    // 64*200 weights k-major
#define O_GN  39952    // 128*68 gh_n staging
#define SMEM_FLOATS 48656
#define XS 68
#define NS 200

__device__ int   g_cnt[2 * N_NODES];
__device__ int   g_slots[(size_t)2 * N_NODES * PAD];
__device__ int   g_et_is_i32;
__device__ int   g_ovf_n;
__device__ int2  g_ovf[OVF_CAP];
__device__ float g_C0[192 * 64];
__device__ float g_C1[192 * 64];
__device__ float g_u0[192];
__device__ float g_u1[192];

__device__ __forceinline__ unsigned tf32c(float x)
{
    unsigned r; asm("cvt.rna.tf32.f32 %0, %1;" : "=r"(r) : "f"(x)); return r;
}
__device__ __forceinline__ float tanh_fast(float x)
{
    float t; asm("tanh.approx.f32 %0, %1;" : "=f"(t) : "f"(x)); return t;
}
__device__ __forceinline__ float sigmoid_fast(float x)
{
    return 0.5f * tanh_fast(0.5f * x) + 0.5f;
}
#define MMA(d, a0, a1, a2, a3, b0, b1) \
    asm volatile("mma.sync.aligned.m16n8k8.row.col.f32.tf32.tf32.f32 " \
        "{%0,%1,%2,%3},{%4,%5,%6,%7},{%8,%9},{%0,%1,%2,%3};" \
        : "+f"((d)[0]), "+f"((d)[1]), "+f"((d)[2]), "+f"((d)[3]) \
        : "r"(a0), "r"(a1), "r"(a2), "r"(a3), "r"(b0), "r"(b1))

// =====================================================================
__global__ void detect_et_kernel(const unsigned char* __restrict__ et, int E)
{
    __shared__ int cnt;
    if (threadIdx.x == 0) { cnt = 0; g_ovf_n = 0; }
    __syncthreads();
    int K = 4096 < E ? 4096 : E;
    int local = 0;
    for (int i = threadIdx.x; i < K; i += blockDim.x) local += (et[i] != 0);
    atomicAdd(&cnt, local);
    __syncthreads();
    if (threadIdx.x == 0) g_et_is_i32 = (cnt < K / 4) ? 1 : 0;
}

__global__ void __launch_bounds__(256) place_kernel(
    const int* __restrict__ src, const int* __restrict__ dst,
    const void* __restrict__ et, int E)
{
    int e = blockIdx.x * blockDim.x + threadIdx.x;
    if (e >= E) return;
    bool t;
    if (g_et_is_i32) t = __ldg((const int*)et + e) != 0;
    else             t = __ldg((const unsigned char*)et + e) != 0;
    int ti = t ? 0 : 1;
    int d = __ldg(dst + e), s = __ldg(src + e);
    int seg = d * 2 + ti;
    int slot = atomicAdd(&g_cnt[seg], 1);
    if (slot < PAD) g_slots[(size_t)seg * PAD + slot] = s;
    else {
        int w = atomicAdd(&g_ovf_n, 1);
        if (w < OVF_CAP) g_ovf[w] = make_int2(seg, s);
    }
}

// C0 = Wih@W0, C1 = Wih@W1, u0 = Wih@b0, u1 = Wih@b1
__global__ void compose_kernel(const float* __restrict__ Wih,
                               const float* __restrict__ W0, const float* __restrict__ W1,
                               const float* __restrict__ b0, const float* __restrict__ b1)
{
    int idx = blockIdx.x * blockDim.x + threadIdx.x;
    if (idx < 192 * 64) {
        int r = idx >> 6, k = idx & 63;
        const float* wr = Wih + r * 64;
        float a0 = 0.f, a1 = 0.f;
        #pragma unroll 8
        for (int j = 0; j < 64; j++) {
            float w = __ldg(wr + j);
            a0 += w * __ldg(W0 + j * 64 + k);
            a1 += w * __ldg(W1 + j * 64 + k);
        }
        g_C0[idx] = a0; g_C1[idx] = a1;
    }
    if (idx < 192) {
        const float* wr = Wih + idx * 64;
        float s0 = 0.f, s1 = 0.f;
        #pragma unroll 8
        for (int j = 0; j < 64; j++) {
            float w = __ldg(wr + j);
            s0 += w * __ldg(b0 + j);
            s1 += w * __ldg(b1 + j);
        }
        g_u0[idx] = s0; g_u1[idx] = s1;
    }
}

// =====================================================================
__device__ __forceinline__ void stage_w192(float* sW, const float* __restrict__ W, int tid)
{
    // sW[k*NS + n] = tf32(W[n*64 + k]),  W is [192,64]
    for (int i = tid; i < 192 * 64; i += TPB) {
        int n = i >> 6, k = i & 63;
        sW[k * NS + n] = __uint_as_float(tf32c(__ldg(W + i)));
    }
}

// one GEMM pass: D[96] += Xtile(this warp's 16 rows) @ Wtile^T (192 cols)
__device__ __forceinline__ void gemm_pass(float* D, const float* sX, const float* sW,
                                          int rA, int tid4, int gid)
{
    #pragma unroll
    for (int kt = 0; kt < 8; kt++) {
        const float* ax = sX + rA * XS + kt * 8 + tid4;
        unsigned a0 = __float_as_uint(ax[0]);
        unsigned a1 = __float_as_uint(ax[8 * XS]);
        unsigned a2 = __float_as_uint(ax[4]);
        unsigned a3 = __float_as_uint(ax[8 * XS + 4]);
        const float* bx = sW + (kt * 8 + tid4) * NS + gid;
        #pragma unroll
        for (int nt = 0; nt < 24; nt++) {
            unsigned b0 = __float_as_uint(bx[nt * 8]);
            unsigned b1 = __float_as_uint(bx[4 * NS + nt * 8]);
            MMA(D + nt * 4, a0, a1, a2, a3, b0, b1);
        }
    }
}

__global__ void __launch_bounds__(TPB, 1) node_kernel(
    const float* __restrict__ feat,
    const float* __restrict__ Whh, const float* __restrict__ Wout,
    const float* __restrict__ bih, const float* __restrict__ bhh,
    const float* __restrict__ bout,
    float* __restrict__ out, int Nn)
{
    extern __shared__ __align__(16) float sm[];
    float* sCnt = sm + O_CNT;
    float* sB   = sm + O_B;
    float* sF   = sm + O_F;
    float* sS0  = sm + O_S0;
    float* sS1  = sm + O_S1;
    float* sW   = sm + O_W;
    float* sGN  = sm + O_GN;

    const int tid  = threadIdx.x;
    const int wid  = tid >> 5;
    const int lane = tid & 31;
    const int gid  = lane >> 2;
    const int tid4 = lane & 3;
    const int rA   = wid * 16 + gid;
    const int n0   = blockIdx.x * NPB;
    const float4* F = (const float4*)feat;

    for (int i = tid; i < 784; i += TPB) {
        float v;
        if (i < 192)      v = g_u0[i];
        else if (i < 384) v = g_u1[i - 192];
        else if (i < 576) v = __ldg(bih + i - 384);
        else if (i < 768) v = __ldg(bhh + i - 576);
        else              v = __ldg(bout + i - 768);
        sB[i] = v;
    }
    for (int i = tid; i < 256; i += TPB) {
        int m = i & 127, t = i >> 7;
        int nn = n0 + m;
        sCnt[t * 128 + m] = (nn < Nn) ? (float)g_cnt[nn * 2 + t] : 0.f;
    }
    // feat tile (tf32)
    for (int i = tid; i < NPB * 16; i += TPB) {
        int r = i >> 4, l = i & 15;
        int nn = n0 + r;
        float4 v = (nn < Nn) ? __ldg(F + (size_t)nn * 16 + l) : make_float4(0.f, 0.f, 0.f, 0.f);
        *(uint4*)(sF + r * XS + l * 4) = make_uint4(tf32c(v.x), tf32c(v.y), tf32c(v.z), tf32c(v.w));
    }
    // gather S0 and S1 (fused, no accumulators live -> high MLP, no spills)
    {
        int ovn = g_ovf_n; if (ovn > OVF_CAP) ovn = OVF_CAP;
        #pragma unroll
        for (int it = 0; it < 16; it++) {
            int i = tid + it * TPB;          // 0..4095
            int ti = i >> 11;
            int idx = i & 2047;
            int r = idx >> 4, l = idx & 15;
            int nn = n0 + r;
            float4 acc = make_float4(0.f, 0.f, 0.f, 0.f);
            if (nn < Nn) {
                int seg = nn * 2 + ti;
                int c = g_cnt[seg];
                int m = c < PAD ? c : PAD;
                const int* sl = g_slots + (size_t)seg * PAD;
                int q = 0;
                for (; q + 4 <= m; q += 4) {
                    int4 s4 = *(const int4*)(sl + q);
                    float4 a = __ldg(F + (size_t)s4.x * 16 + l);
                    float4 b = __ldg(F + (size_t)s4.y * 16 + l);
                    float4 c2 = __ldg(F + (size_t)s4.z * 16 + l);
                    float4 e = __ldg(F + (size_t)s4.w * 16 + l);
                    acc.x += (a.x + b.x) + (c2.x + e.x);
                    acc.y += (a.y + b.y) + (c2.y + e.y);
                    acc.z += (a.z + b.z) + (c2.z + e.z);
                    acc.w += (a.w + b.w) + (c2.w + e.w);
                }
                for (; q < m; q++) {
                    float4 a = __ldg(F + (size_t)sl[q] * 16 + l);
                    acc.x += a.x; acc.y += a.y; acc.z += a.z; acc.w += a.w;
                }
                for (int o = 0; o < ovn; o++) {
                    int2 ov = g_ovf[o];
                    if (ov.x == seg) {
                        float4 v = __ldg(F + (size_t)ov.y * 16 + l);
                        acc.x += v.x; acc.y += v.y; acc.z += v.z; acc.w += v.w;
                    }
                }
            }
            float* dstX = ti ? sS1 : sS0;
            *(uint4*)(dstX + r * XS + l * 4) =
                make_uint4(tf32c(acc.x), tf32c(acc.y), tf32c(acc.z), tf32c(acc.w));
        }
    }
    stage_w192(sW, Whh, tid);
    __syncthreads();

    // ---- pass 1: D = feat @ Whh^T ----
    float D[96];
    #pragma unroll
    for (int q = 0; q < 96; q++) D[q] = 0.f;
    gemm_pass(D, sF, sW, rA, tid4, gid);
    // dump gh_n (cols 128..191) to sGN, zero those accumulators
    #pragma unroll
    for (int nt = 16; nt < 24; nt++) {
        *(float2*)(sGN + rA * XS + (nt - 16) * 8 + tid4 * 2) =
            make_float2(D[nt*4], D[nt*4+1]);
        *(float2*)(sGN + (rA + 8) * XS + (nt - 16) * 8 + tid4 * 2) =
            make_float2(D[nt*4+2], D[nt*4+3]);
        D[nt*4] = D[nt*4+1] = D[nt*4+2] = D[nt*4+3] = 0.f;
    }
    __syncthreads();

    // ---- pass 2: D += S0 @ C0^T ----
    stage_w192(sW, g_C0, tid);
    __syncthreads();
    gemm_pass(D, sS0, sW, rA, tid4, gid);
    __syncthreads();

    // ---- pass 3: D += S1 @ C1^T ----
    stage_w192(sW, g_C1, tid);
    __syncthreads();
    gemm_pass(D, sS1, sW, rA, tid4, gid);

    // ---- elementwise GRU (fp32); h -> sF (own cells) ----
    #pragma unroll
    for (int j = 0; j < 2; j++) {
        const int row = rA + j * 8;
        const float c0m = sCnt[row], c1m = sCnt[128 + row];
        const int valid = (n0 + row) < Nn;
        #pragma unroll
        for (int nt = 0; nt < 8; nt++) {
            float2 fv = make_float2(0.f, 0.f);
            if (valid)
                fv = *(const float2*)(feat + (size_t)(n0 + row) * 64 + nt * 8 + tid4 * 2);
            #pragma unroll
            for (int e = 0; e < 2; e++) {
                int c = nt * 8 + tid4 * 2 + e;
                float gr = D[nt * 4 + j * 2 + e]        + c0m * sB[c]       + c1m * sB[192 + c]
                         + sB[384 + c] + sB[576 + c];
                float gz = D[(8 + nt) * 4 + j * 2 + e]  + c0m * sB[64 + c]  + c1m * sB[256 + c]
                         + sB[448 + c] + sB[640 + c];
                float gn = D[(16 + nt) * 4 + j * 2 + e] + c0m * sB[128 + c] + c1m * sB[320 + c]
                         + sB[512 + c];
                float hn = sGN[row * XS + c] + sB[704 + c];
                float rr = sigmoid_fast(gr);
                float zz = sigmoid_fast(gz);
                float nn = tanh_fast(gn + rr * hn);
                float f  = (e == 0) ? fv.x : fv.y;
                sF[row * XS + c] = nn + zz * (f - nn);
            }
        }
    }
    __syncthreads();

    // ---- classifier (scalar fp32): out = h @ Wout^T + bout ----
    for (int i = tid; i < 1024; i += TPB) {
        int c = i >> 6, k = i & 63;
        sW[k * 16 + c] = __ldg(Wout + i);
    }
    __syncthreads();
    {
        int r  = tid >> 1;
        int cb = (tid & 1) * 8;
        float o[8];
        #pragma unroll
        for (int c = 0; c < 8; c++) o[c] = sB[768 + cb + c];
        #pragma unroll 4
        for (int k = 0; k < 64; k++) {
            float hv = sF[r * XS + k];
            float4 w0 = *(const float4*)(sW + k * 16 + cb);
            float4 w1 = *(const float4*)(sW + k * 16 + cb + 4);
            o[0] += hv * w0.x; o[1] += hv * w0.y; o[2] += hv * w0.z; o[3] += hv * w0.w;
            o[4] += hv * w1.x; o[5] += hv * w1.y; o[6] += hv * w1.z; o[7] += hv * w1.w;
        }
        if (n0 + r < Nn) {
            float4* po = (float4*)(out + (size_t)(n0 + r) * 16 + cb);
            po[0] = make_float4(o[0], o[1], o[2], o[3]);
            po[1] = make_float4(o[4], o[5], o[6], o[7]);
        }
    }
}

// =====================================================================
extern "C" void kernel_launch(void* const* d_in, const int* in_sizes, int n_in,
                              void* d_out, int out_size)
{
    const float* feat = (const float*)d_in[0];
    const int*   src  = (const int*)d_in[1];
    const int*   dst  = (const int*)d_in[2];
    const void*  et   = d_in[3];
    const float* W0   = (const float*)d_in[4];
    const float* b0   = (const float*)d_in[5];
    const float* W1   = (const float*)d_in[6];
    const float* b1   = (const float*)d_in[7];
    const float* Wih  = (const float*)d_in[8];
    const float* Whh  = (const float*)d_in[9];
    const float* bih  = (const float*)d_in[10];
    const float* bhh  = (const float*)d_in[11];
    const float* Wout = (const float*)d_in[12];
    const float* bout = (const float*)d_in[13];
    float* out = (float*)d_out;

    const int E  = in_sizes[1];
    const int Nn = in_sizes[0] / HDIM;

    void* p;
    cudaGetSymbolAddress(&p, g_cnt);
    cudaMemsetAsync(p, 0, sizeof(int) * 2 * N_NODES);

    detect_et_kernel<<<1, 256>>>((const unsigned char*)et, E);
    place_kernel<<<(E + 255) / 256, 256>>>(src, dst, et, E);
    compose_kernel<<<48, 256>>>(Wih, W0, W1, b0, b1);

    size_t smem = SMEM_FLOATS * sizeof(float);   // 194624 B
    cudaFuncSetAttribute(node_kernel, cudaFuncAttributeMaxDynamicSharedMemorySize, (int)smem);
    int nb = (Nn + NPB - 1) / NPB;
    node_kernel<<<nb, TPB, smem>>>(feat, Whh, Wout, bih, bhh, bout, out, Nn);
}

// round 14
// speedup vs baseline: 1.0171x; 1.0047x over previous
#include <cuda_runtime.h>
#include <math.h>

#define N_NODES 100000
#define HDIM 64
#define NPB  128
#define TPB  256
#define PAD  32
#define OVF_CAP 65536

// smem layout (float indices)
#define O_CNT 0        // 256
#define O_B   256      // 784  (u0|u1|bih|bhh|bout)
#define O_F   1040     // 128*68 feat tile (later h)
#define O_S0  9744     // 128*68 S0
#define O_S1  18448    // 128*68 S1
#define O_W   27152    // 64*200 weights k-major
#define O_GN  39952    // 128*68 gh_n staging
#define SMEM_FLOATS 48656
#define XS 68
#define NS 200

__device__ int   g_cnt[2 * N_NODES];
__device__ int   g_slots[(size_t)2 * N_NODES * PAD];
__device__ int   g_et_is_i32;
__device__ int   g_ovf_n;
__device__ int2  g_ovf[OVF_CAP];
__device__ float g_C0[192 * 64];
__device__ float g_C1[192 * 64];
__device__ float g_u0[192];
__device__ float g_u1[192];

__device__ __forceinline__ unsigned tf32c(float x)
{
    unsigned r; asm("cvt.rna.tf32.f32 %0, %1;" : "=r"(r) : "f"(x)); return r;
}
__device__ __forceinline__ float tanh_fast(float x)
{
    float t; asm("tanh.approx.f32 %0, %1;" : "=f"(t) : "f"(x)); return t;
}
__device__ __forceinline__ float sigmoid_fast(float x)
{
    return 0.5f * tanh_fast(0.5f * x) + 0.5f;
}
#define MMA(d, a0, a1, a2, a3, b0, b1) \
    asm volatile("mma.sync.aligned.m16n8k8.row.col.f32.tf32.tf32.f32 " \
        "{%0,%1,%2,%3},{%4,%5,%6,%7},{%8,%9},{%0,%1,%2,%3};" \
        : "+f"((d)[0]), "+f"((d)[1]), "+f"((d)[2]), "+f"((d)[3]) \
        : "r"(a0), "r"(a1), "r"(a2), "r"(a3), "r"(b0), "r"(b1))

// =====================================================================
__global__ void detect_et_kernel(const unsigned char* __restrict__ et, int E)
{
    __shared__ int cnt;
    if (threadIdx.x == 0) { cnt = 0; g_ovf_n = 0; }
    __syncthreads();
    int K = 4096 < E ? 4096 : E;
    int local = 0;
    for (int i = threadIdx.x; i < K; i += blockDim.x) local += (et[i] != 0);
    atomicAdd(&cnt, local);
    __syncthreads();
    if (threadIdx.x == 0) g_et_is_i32 = (cnt < K / 4) ? 1 : 0;
}

__global__ void __launch_bounds__(256) place_kernel(
    const int* __restrict__ src, const int* __restrict__ dst,
    const void* __restrict__ et, int E)
{
    int e = blockIdx.x * blockDim.x + threadIdx.x;
    if (e >= E) return;
    bool t;
    if (g_et_is_i32) t = __ldg((const int*)et + e) != 0;
    else             t = __ldg((const unsigned char*)et + e) != 0;
    int ti = t ? 0 : 1;
    int d = __ldg(dst + e), s = __ldg(src + e);
    int seg = d * 2 + ti;
    int slot = atomicAdd(&g_cnt[seg], 1);
    if (slot < PAD) g_slots[(size_t)seg * PAD + slot] = s;
    else {
        int w = atomicAdd(&g_ovf_n, 1);
        if (w < OVF_CAP) g_ovf[w] = make_int2(seg, s);
    }
}

// C0 = Wih@W0, C1 = Wih@W1, u0 = Wih@b0, u1 = Wih@b1
__global__ void compose_kernel(const float* __restrict__ Wih,
                               const float* __restrict__ W0, const float* __restrict__ W1,
                               const float* __restrict__ b0, const float* __restrict__ b1)
{
    int idx = blockIdx.x * blockDim.x + threadIdx.x;
    if (idx < 192 * 64) {
        int r = idx >> 6, k = idx & 63;
        const float* wr = Wih + r * 64;
        float a0 = 0.f, a1 = 0.f;
        #pragma unroll 8
        for (int j = 0; j < 64; j++) {
            float w = __ldg(wr + j);
            a0 += w * __ldg(W0 + j * 64 + k);
            a1 += w * __ldg(W1 + j * 64 + k);
        }
        g_C0[idx] = a0; g_C1[idx] = a1;
    }
    if (idx < 192) {
        const float* wr = Wih + idx * 64;
        float s0 = 0.f, s1 = 0.f;
        #pragma unroll 8
        for (int j = 0; j < 64; j++) {
            float w = __ldg(wr + j);
            s0 += w * __ldg(b0 + j);
            s1 += w * __ldg(b1 + j);
        }
        g_u0[idx] = s0; g_u1[idx] = s1;
    }
}

// =====================================================================
__device__ __forceinline__ void stage_w192(float* sW, const float* __restrict__ W, int tid)
{
    // sW[k*NS + n] = tf32(W[n*64 + k]),  W is [192,64]
    for (int i = tid; i < 192 * 64; i += TPB) {
        int n = i >> 6, k = i & 63;
        sW[k * NS + n] = __uint_as_float(tf32c(__ldg(W + i)));
    }
}

// one GEMM pass: D[96] += Xtile(this warp's 16 rows) @ Wtile^T (192 cols)
__device__ __forceinline__ void gemm_pass(float* D, const float* sX, const float* sW,
                                          int rA, int tid4, int gid)
{
    #pragma unroll
    for (int kt = 0; kt < 8; kt++) {
        const float* ax = sX + rA * XS + kt * 8 + tid4;
        unsigned a0 = __float_as_uint(ax[0]);
        unsigned a1 = __float_as_uint(ax[8 * XS]);
        unsigned a2 = __float_as_uint(ax[4]);
        unsigned a3 = __float_as_uint(ax[8 * XS + 4]);
        const float* bx = sW + (kt * 8 + tid4) * NS + gid;
        #pragma unroll
        for (int nt = 0; nt < 24; nt++) {
            unsigned b0 = __float_as_uint(bx[nt * 8]);
            unsigned b1 = __float_as_uint(bx[4 * NS + nt * 8]);
            MMA(D + nt * 4, a0, a1, a2, a3, b0, b1);
        }
    }
}

__global__ void __launch_bounds__(TPB, 1) node_kernel(
    const float* __restrict__ feat,
    const float* __restrict__ Whh, const float* __restrict__ Wout,
    const float* __restrict__ bih, const float* __restrict__ bhh,
    const float* __restrict__ bout,
    float* __restrict__ out, int Nn)
{
    extern __shared__ __align__(16) float sm[];
    float* sCnt = sm + O_CNT;
    float* sB   = sm + O_B;
    float* sF   = sm + O_F;
    float* sS0  = sm + O_S0;
    float* sS1  = sm + O_S1;
    float* sW   = sm + O_W;
    float* sGN  = sm + O_GN;

    const int tid  = threadIdx.x;
    const int wid  = tid >> 5;
    const int lane = tid & 31;
    const int gid  = lane >> 2;
    const int tid4 = lane & 3;
    const int rA   = wid * 16 + gid;
    const int n0   = blockIdx.x * NPB;
    const float4* F = (const float4*)feat;

    for (int i = tid; i < 784; i += TPB) {
        float v;
        if (i < 192)      v = g_u0[i];
        else if (i < 384) v = g_u1[i - 192];
        else if (i < 576) v = __ldg(bih + i - 384);
        else if (i < 768) v = __ldg(bhh + i - 576);
        else              v = __ldg(bout + i - 768);
        sB[i] = v;
    }
    for (int i = tid; i < 256; i += TPB) {
        int m = i & 127, t = i >> 7;
        int nn = n0 + m;
        sCnt[t * 128 + m] = (nn < Nn) ? (float)g_cnt[nn * 2 + t] : 0.f;
    }
    // feat tile (tf32)
    for (int i = tid; i < NPB * 16; i += TPB) {
        int r = i >> 4, l = i & 15;
        int nn = n0 + r;
        float4 v = (nn < Nn) ? __ldg(F + (size_t)nn * 16 + l) : make_float4(0.f, 0.f, 0.f, 0.f);
        *(uint4*)(sF + r * XS + l * 4) = make_uint4(tf32c(v.x), tf32c(v.y), tf32c(v.z), tf32c(v.w));
    }
    // gather S0 and S1 (fused, no accumulators live -> high MLP, no spills)
    {
        int ovn = g_ovf_n; if (ovn > OVF_CAP) ovn = OVF_CAP;
        #pragma unroll
        for (int it = 0; it < 16; it++) {
            int i = tid + it * TPB;          // 0..4095
            int ti = i >> 11;
            int idx = i & 2047;
            int r = idx >> 4, l = idx & 15;
            int nn = n0 + r;
            float4 acc = make_float4(0.f, 0.f, 0.f, 0.f);
            if (nn < Nn) {
                int seg = nn * 2 + ti;
                int c = g_cnt[seg];
                int m = c < PAD ? c : PAD;
                const int* sl = g_slots + (size_t)seg * PAD;
                int q = 0;
                for (; q + 4 <= m; q += 4) {
                    int4 s4 = *(const int4*)(sl + q);
                    float4 a = __ldg(F + (size_t)s4.x * 16 + l);
                    float4 b = __ldg(F + (size_t)s4.y * 16 + l);
                    float4 c2 = __ldg(F + (size_t)s4.z * 16 + l);
                    float4 e = __ldg(F + (size_t)s4.w * 16 + l);
                    acc.x += (a.x + b.x) + (c2.x + e.x);
                    acc.y += (a.y + b.y) + (c2.y + e.y);
                    acc.z += (a.z + b.z) + (c2.z + e.z);
                    acc.w += (a.w + b.w) + (c2.w + e.w);
                }
                for (; q < m; q++) {
                    float4 a = __ldg(F + (size_t)sl[q] * 16 + l);
                    acc.x += a.x; acc.y += a.y; acc.z += a.z; acc.w += a.w;
                }
                for (int o = 0; o < ovn; o++) {
                    int2 ov = g_ovf[o];
                    if (ov.x == seg) {
                        float4 v = __ldg(F + (size_t)ov.y * 16 + l);
                        acc.x += v.x; acc.y += v.y; acc.z += v.z; acc.w += v.w;
                    }
                }
            }
            float* dstX = ti ? sS1 : sS0;
            *(uint4*)(dstX + r * XS + l * 4) =
                make_uint4(tf32c(acc.x), tf32c(acc.y), tf32c(acc.z), tf32c(acc.w));
        }
    }
    stage_w192(sW, Whh, tid);
    __syncthreads();

    // ---- pass 1: D = feat @ Whh^T ----
    float D[96];
    #pragma unroll
    for (int q = 0; q < 96; q++) D[q] = 0.f;
    gemm_pass(D, sF, sW, rA, tid4, gid);
    // dump gh_n (cols 128..191) to sGN, zero those accumulators
    #pragma unroll
    for (int nt = 16; nt < 24; nt++) {
        *(float2*)(sGN + rA * XS + (nt - 16) * 8 + tid4 * 2) =
            make_float2(D[nt*4], D[nt*4+1]);
        *(float2*)(sGN + (rA + 8) * XS + (nt - 16) * 8 + tid4 * 2) =
            make_float2(D[nt*4+2], D[nt*4+3]);
        D[nt*4] = D[nt*4+1] = D[nt*4+2] = D[nt*4+3] = 0.f;
    }
    __syncthreads();

    // ---- pass 2: D += S0 @ C0^T ----
    stage_w192(sW, g_C0, tid);
    __syncthreads();
    gemm_pass(D, sS0, sW, rA, tid4, gid);
    __syncthreads();

    // ---- pass 3: D += S1 @ C1^T ----
    stage_w192(sW, g_C1, tid);
    __syncthreads();
    gemm_pass(D, sS1, sW, rA, tid4, gid);

    // ---- elementwise GRU (fp32); h -> sF (own cells) ----
    #pragma unroll
    for (int j = 0; j < 2; j++) {
        const int row = rA + j * 8;
        const float c0m = sCnt[row], c1m = sCnt[128 + row];
        const int valid = (n0 + row) < Nn;
        #pragma unroll
        for (int nt = 0; nt < 8; nt++) {
            float2 fv = make_float2(0.f, 0.f);
            if (valid)
                fv = *(const float2*)(feat + (size_t)(n0 + row) * 64 + nt * 8 + tid4 * 2);
            #pragma unroll
            for (int e = 0; e < 2; e++) {
                int c = nt * 8 + tid4 * 2 + e;
                float gr = D[nt * 4 + j * 2 + e]        + c0m * sB[c]       + c1m * sB[192 + c]
                         + sB[384 + c] + sB[576 + c];
                float gz = D[(8 + nt) * 4 + j * 2 + e]  + c0m * sB[64 + c]  + c1m * sB[256 + c]
                         + sB[448 + c] + sB[640 + c];
                float gn = D[(16 + nt) * 4 + j * 2 + e] + c0m * sB[128 + c] + c1m * sB[320 + c]
                         + sB[512 + c];
                float hn = sGN[row * XS + c] + sB[704 + c];
                float rr = sigmoid_fast(gr);
                float zz = sigmoid_fast(gz);
                float nn = tanh_fast(gn + rr * hn);
                float f  = (e == 0) ? fv.x : fv.y;
                sF[row * XS + c] = nn + zz * (f - nn);
            }
        }
    }
    __syncthreads();

    // ---- classifier (scalar fp32): out = h @ Wout^T + bout ----
    for (int i = tid; i < 1024; i += TPB) {
        int c = i >> 6, k = i & 63;
        sW[k * 16 + c] = __ldg(Wout + i);
    }
    __syncthreads();
    {
        int r  = tid >> 1;
        int cb = (tid & 1) * 8;
        float o[8];
        #pragma unroll
        for (int c = 0; c < 8; c++) o[c] = sB[768 + cb + c];
        #pragma unroll 4
        for (int k = 0; k < 64; k++) {
            float hv = sF[r * XS + k];
            float4 w0 = *(const float4*)(sW + k * 16 + cb);
            float4 w1 = *(const float4*)(sW + k * 16 + cb + 4);
            o[0] += hv * w0.x; o[1] += hv * w0.y; o[2] += hv * w0.z; o[3] += hv * w0.w;
            o[4] += hv * w1.x; o[5] += hv * w1.y; o[6] += hv * w1.z; o[7] += hv * w1.w;
        }
        if (n0 + r < Nn) {
            float4* po = (float4*)(out + (size_t)(n0 + r) * 16 + cb);
            po[0] = make_float4(o[0], o[1], o[2], o[3]);
            po[1] = make_float4(o[4], o[5], o[6], o[7]);
        }
    }
}

// =====================================================================
extern "C" void kernel_launch(void* const* d_in, const int* in_sizes, int n_in,
                              void* d_out, int out_size)
{
    const float* feat = (const float*)d_in[0];
    const int*   src  = (const int*)d_in[1];
    const int*   dst  = (const int*)d_in[2];
    const void*  et   = d_in[3];
    const float* W0   = (const float*)d_in[4];
    const float* b0   = (const float*)d_in[5];
    const float* W1   = (const float*)d_in[6];
    const float* b1   = (const float*)d_in[7];
    const float* Wih  = (const float*)d_in[8];
    const float* Whh  = (const float*)d_in[9];
    const float* bih  = (const float*)d_in[10];
    const float* bhh  = (const float*)d_in[11];
    const float* Wout = (const float*)d_in[12];
    const float* bout = (const float*)d_in[13];
    float* out = (float*)d_out;

    const int E  = in_sizes[1];
    const int Nn = in_sizes[0] / HDIM;

    void* p;
    cudaGetSymbolAddress(&p, g_cnt);
    cudaMemsetAsync(p, 0, sizeof(int) * 2 * N_NODES);

    detect_et_kernel<<<1, 256>>>((const unsigned char*)et, E);
    place_kernel<<<(E + 255) / 256, 256>>>(src, dst, et, E);
    compose_kernel<<<48, 256>>>(Wih, W0, W1, b0, b1);

    size_t smem = SMEM_FLOATS * sizeof(float);   // 194624 B
    cudaFuncSetAttribute(node_kernel, cudaFuncAttributeMaxDynamicSharedMemorySize, (int)smem);
    int nb = (Nn + NPB - 1) / NPB;
    node_kernel<<<nb, TPB, smem>>>(feat, Whh, Wout, bih, bhh, bout, out, Nn);
}

// round 15
// speedup vs baseline: 1.2965x; 1.2747x over previous
#include <cuda_runtime.h>
#include <math.h>

#define N_NODES 100000
#define HDIM 64
#define NPB  128
#define TPB  512
#define PAD  32
#define OVF_CAP 65536

// smem layout (float indices)
#define O_CNT 0        // 256
#define O_B   256      // 784  (u0|u1|bih|bhh|bout)
#define O_F   1040     // 128*68 feat tile (later h)
#define O_S0  9744     // 128*68 S0
#define O_S1  18448    // 128*68 S1
#define O_W   27152    // 64*200 weights k-major
#define O_GN  39952    // 128*68 gh_n staging
#define SMEM_FLOATS 48656
#define XS 68
#define NS 200

__device__ int   g_cnt[2 * N_NODES];
__device__ int   g_slots[(size_t)2 * N_NODES * PAD];
__device__ int   g_et_is_i32;
__device__ int   g_ovf_n;
__device__ int2  g_ovf[OVF_CAP];
__device__ float g_C0[192 * 64];
__device__ float g_C1[192 * 64];
__device__ float g_u0[192];
__device__ float g_u1[192];

__device__ __forceinline__ unsigned tf32c(float x)
{
    unsigned r; asm("cvt.rna.tf32.f32 %0, %1;" : "=r"(r) : "f"(x)); return r;
}
__device__ __forceinline__ float tanh_fast(float x)
{
    float t; asm("tanh.approx.f32 %0, %1;" : "=f"(t) : "f"(x)); return t;
}
__device__ __forceinline__ float sigmoid_fast(float x)
{
    return 0.5f * tanh_fast(0.5f * x) + 0.5f;
}
#define MMA(d, a0, a1, a2, a3, b0, b1) \
    asm volatile("mma.sync.aligned.m16n8k8.row.col.f32.tf32.tf32.f32 " \
        "{%0,%1,%2,%3},{%4,%5,%6,%7},{%8,%9},{%0,%1,%2,%3};" \
        : "+f"((d)[0]), "+f"((d)[1]), "+f"((d)[2]), "+f"((d)[3]) \
        : "r"(a0), "r"(a1), "r"(a2), "r"(a3), "r"(b0), "r"(b1))

// =====================================================================
__global__ void detect_et_kernel(const unsigned char* __restrict__ et, int E)
{
    __shared__ int cnt;
    if (threadIdx.x == 0) { cnt = 0; g_ovf_n = 0; }
    __syncthreads();
    int K = 4096 < E ? 4096 : E;
    int local = 0;
    for (int i = threadIdx.x; i < K; i += blockDim.x) local += (et[i] != 0);
    atomicAdd(&cnt, local);
    __syncthreads();
    if (threadIdx.x == 0) g_et_is_i32 = (cnt < K / 4) ? 1 : 0;
}

__global__ void __launch_bounds__(256) place_kernel(
    const int* __restrict__ src, const int* __restrict__ dst,
    const void* __restrict__ et, int E)
{
    int e = blockIdx.x * blockDim.x + threadIdx.x;
    if (e >= E) return;
    bool t;
    if (g_et_is_i32) t = __ldg((const int*)et + e) != 0;
    else             t = __ldg((const unsigned char*)et + e) != 0;
    int ti = t ? 0 : 1;
    int d = __ldg(dst + e), s = __ldg(src + e);
    int seg = d * 2 + ti;
    int slot = atomicAdd(&g_cnt[seg], 1);
    if (slot < PAD) g_slots[(size_t)seg * PAD + slot] = s;
    else {
        int w = atomicAdd(&g_ovf_n, 1);
        if (w < OVF_CAP) g_ovf[w] = make_int2(seg, s);
    }
}

// C0 = Wih@W0, C1 = Wih@W1, u0 = Wih@b0, u1 = Wih@b1
__global__ void compose_kernel(const float* __restrict__ Wih,
                               const float* __restrict__ W0, const float* __restrict__ W1,
                               const float* __restrict__ b0, const float* __restrict__ b1)
{
    int idx = blockIdx.x * blockDim.x + threadIdx.x;
    if (idx < 192 * 64) {
        int r = idx >> 6, k = idx & 63;
        const float* wr = Wih + r * 64;
        float a0 = 0.f, a1 = 0.f;
        #pragma unroll 8
        for (int j = 0; j < 64; j++) {
            float w = __ldg(wr + j);
            a0 += w * __ldg(W0 + j * 64 + k);
            a1 += w * __ldg(W1 + j * 64 + k);
        }
        g_C0[idx] = a0; g_C1[idx] = a1;
    }
    if (idx < 192) {
        const float* wr = Wih + idx * 64;
        float s0 = 0.f, s1 = 0.f;
        #pragma unroll 8
        for (int j = 0; j < 64; j++) {
            float w = __ldg(wr + j);
            s0 += w * __ldg(b0 + j);
            s1 += w * __ldg(b1 + j);
        }
        g_u0[idx] = s0; g_u1[idx] = s1;
    }
}

// =====================================================================
__device__ __forceinline__ void stage_w192(float* sW, const float* __restrict__ W, int tid)
{
    // sW[k*NS + n] = tf32(W[n*64 + k]),  W is [192,64]
    for (int i = tid; i < 192 * 64; i += TPB) {
        int n = i >> 6, k = i & 63;
        sW[k * NS + n] = __uint_as_float(tf32c(__ldg(W + i)));
    }
}

// GEMM pass: D[48] += Xtile(16 rows at rA..) @ Wtile^T (this warp's 12 n-tiles)
// n-tile q of gate g lives at n-col g*64 + h*32 + q*8
__device__ __forceinline__ void gemm_pass(float* D, const float* sX, const float* sW,
                                          int rA, int tid4, int gid, int h)
{
    #pragma unroll
    for (int kt = 0; kt < 8; kt++) {
        const float* ax = sX + rA * XS + kt * 8 + tid4;
        unsigned a0 = __float_as_uint(ax[0]);
        unsigned a1 = __float_as_uint(ax[8 * XS]);
        unsigned a2 = __float_as_uint(ax[4]);
        unsigned a3 = __float_as_uint(ax[8 * XS + 4]);
        const float* bx = sW + (kt * 8 + tid4) * NS + gid + h * 32;
        #pragma unroll
        for (int g = 0; g < 3; g++) {
            #pragma unroll
            for (int q = 0; q < 4; q++) {
                int ncol = g * 64 + q * 8;
                unsigned b0 = __float_as_uint(bx[ncol]);
                unsigned b1 = __float_as_uint(bx[4 * NS + ncol]);
                MMA(D + (g * 4 + q) * 4, a0, a1, a2, a3, b0, b1);
            }
        }
    }
}

__global__ void __launch_bounds__(TPB, 1) node_kernel(
    const float* __restrict__ feat,
    const float* __restrict__ Whh, const float* __restrict__ Wout,
    const float* __restrict__ bih, const float* __restrict__ bhh,
    const float* __restrict__ bout,
    float* __restrict__ out, int Nn)
{
    extern __shared__ __align__(16) float sm[];
    float* sCnt = sm + O_CNT;
    float* sB   = sm + O_B;
    float* sF   = sm + O_F;
    float* sS0  = sm + O_S0;
    float* sS1  = sm + O_S1;
    float* sW   = sm + O_W;
    float* sGN  = sm + O_GN;

    const int tid  = threadIdx.x;
    const int wid  = tid >> 5;
    const int lane = tid & 31;
    const int gid  = lane >> 2;
    const int tid4 = lane & 3;
    const int pair = wid >> 1;           // 0..7: 16-row tile index
    const int h    = wid & 1;            // N-half within gates
    const int rA   = pair * 16 + gid;
    const int n0   = blockIdx.x * NPB;
    const float4* F = (const float4*)feat;

    for (int i = tid; i < 784; i += TPB) {
        float v;
        if (i < 192)      v = g_u0[i];
        else if (i < 384) v = g_u1[i - 192];
        else if (i < 576) v = __ldg(bih + i - 384);
        else if (i < 768) v = __ldg(bhh + i - 576);
        else              v = __ldg(bout + i - 768);
        sB[i] = v;
    }
    for (int i = tid; i < 256; i += TPB) {
        int m = i & 127, t = i >> 7;
        int nn = n0 + m;
        sCnt[t * 128 + m] = (nn < Nn) ? (float)g_cnt[nn * 2 + t] : 0.f;
    }
    // feat tile (tf32)
    for (int i = tid; i < NPB * 16; i += TPB) {
        int r = i >> 4, l = i & 15;
        int nn = n0 + r;
        float4 v = (nn < Nn) ? __ldg(F + (size_t)nn * 16 + l) : make_float4(0.f, 0.f, 0.f, 0.f);
        *(uint4*)(sF + r * XS + l * 4) = make_uint4(tf32c(v.x), tf32c(v.y), tf32c(v.z), tf32c(v.w));
    }
    // gather S0 and S1 (fused)
    {
        int ovn = g_ovf_n; if (ovn > OVF_CAP) ovn = OVF_CAP;
        #pragma unroll 2
        for (int it = 0; it < 8; it++) {
            int i = tid + it * TPB;          // 0..4095
            int ti = i >> 11;
            int idx = i & 2047;
            int r = idx >> 4, l = idx & 15;
            int nn = n0 + r;
            float4 acc = make_float4(0.f, 0.f, 0.f, 0.f);
            if (nn < Nn) {
                int seg = nn * 2 + ti;
                int c = g_cnt[seg];
                int m = c < PAD ? c : PAD;
                const int* sl = g_slots + (size_t)seg * PAD;
                int q = 0;
                for (; q + 4 <= m; q += 4) {
                    int4 s4 = *(const int4*)(sl + q);
                    float4 a = __ldg(F + (size_t)s4.x * 16 + l);
                    float4 b = __ldg(F + (size_t)s4.y * 16 + l);
                    float4 c2 = __ldg(F + (size_t)s4.z * 16 + l);
                    float4 e = __ldg(F + (size_t)s4.w * 16 + l);
                    acc.x += (a.x + b.x) + (c2.x + e.x);
                    acc.y += (a.y + b.y) + (c2.y + e.y);
                    acc.z += (a.z + b.z) + (c2.z + e.z);
                    acc.w += (a.w + b.w) + (c2.w + e.w);
                }
                for (; q < m; q++) {
                    float4 a = __ldg(F + (size_t)sl[q] * 16 + l);
                    acc.x += a.x; acc.y += a.y; acc.z += a.z; acc.w += a.w;
                }
                for (int o = 0; o < ovn; o++) {
                    int2 ov = g_ovf[o];
                    if (ov.x == seg) {
                        float4 v = __ldg(F + (size_t)ov.y * 16 + l);
                        acc.x += v.x; acc.y += v.y; acc.z += v.z; acc.w += v.w;
                    }
                }
            }
            float* dstX = ti ? sS1 : sS0;
            *(uint4*)(dstX + r * XS + l * 4) =
                make_uint4(tf32c(acc.x), tf32c(acc.y), tf32c(acc.z), tf32c(acc.w));
        }
    }
    stage_w192(sW, Whh, tid);
    __syncthreads();

    // ---- pass 1: D = feat @ Whh^T (this warp's 12 n-tiles) ----
    float D[48];
    #pragma unroll
    for (int q = 0; q < 48; q++) D[q] = 0.f;
    gemm_pass(D, sF, sW, rA, tid4, gid, h);
    // dump gh_n (gate g=2) to sGN, zero those accumulators
    #pragma unroll
    for (int q = 0; q < 4; q++) {
        int di = (8 + q) * 4;
        int cb = h * 32 + q * 8 + tid4 * 2;
        *(float2*)(sGN + rA * XS + cb)       = make_float2(D[di],   D[di+1]);
        *(float2*)(sGN + (rA + 8) * XS + cb) = make_float2(D[di+2], D[di+3]);
        D[di] = D[di+1] = D[di+2] = D[di+3] = 0.f;
    }
    __syncthreads();

    // ---- pass 2: D += S0 @ C0^T ----
    stage_w192(sW, g_C0, tid);
    __syncthreads();
    gemm_pass(D, sS0, sW, rA, tid4, gid, h);
    __syncthreads();

    // ---- pass 3: D += S1 @ C1^T ----
    stage_w192(sW, g_C1, tid);
    __syncthreads();
    gemm_pass(D, sS1, sW, rA, tid4, gid, h);

    // ---- elementwise GRU (fp32); h -> sF (own cells) ----
    #pragma unroll
    for (int j = 0; j < 2; j++) {
        const int row = rA + j * 8;
        const float c0m = sCnt[row], c1m = sCnt[128 + row];
        const int valid = (n0 + row) < Nn;
        #pragma unroll
        for (int q = 0; q < 4; q++) {
            float2 fv = make_float2(0.f, 0.f);
            int c = h * 32 + q * 8 + tid4 * 2;      // 0..63 within gate
            if (valid)
                fv = *(const float2*)(feat + (size_t)(n0 + row) * 64 + c);
            #pragma unroll
            for (int e = 0; e < 2; e++) {
                int cc = c + e;
                float gr = D[q * 4 + j * 2 + e]       + c0m * sB[cc]       + c1m * sB[192 + cc]
                         + sB[384 + cc] + sB[576 + cc];
                float gz = D[(4 + q) * 4 + j * 2 + e] + c0m * sB[64 + cc]  + c1m * sB[256 + cc]
                         + sB[448 + cc] + sB[640 + cc];
                float gn = D[(8 + q) * 4 + j * 2 + e] + c0m * sB[128 + cc] + c1m * sB[320 + cc]
                         + sB[512 + cc];
                float hn = sGN[row * XS + cc] + sB[704 + cc];
                float rr = sigmoid_fast(gr);
                float zz = sigmoid_fast(gz);
                float nn = tanh_fast(gn + rr * hn);
                float f  = (e == 0) ? fv.x : fv.y;
                sF[row * XS + cc] = nn + zz * (f - nn);
            }
        }
    }
    __syncthreads();

    // ---- classifier (scalar fp32): out = h @ Wout^T + bout ----
    for (int i = tid; i < 1024; i += TPB) {
        int c = i >> 6, k = i & 63;
        sW[k * 16 + c] = __ldg(Wout + i);
    }
    __syncthreads();
    {
        int r  = tid >> 2;
        int cb = (tid & 3) * 4;
        float o[4];
        #pragma unroll
        for (int c = 0; c < 4; c++) o[c] = sB[768 + cb + c];
        #pragma unroll 4
        for (int k = 0; k < 64; k++) {
            float hv = sF[r * XS + k];
            float4 w0 = *(const float4*)(sW + k * 16 + cb);
            o[0] += hv * w0.x; o[1] += hv * w0.y; o[2] += hv * w0.z; o[3] += hv * w0.w;
        }
        if (n0 + r < Nn)
            *(float4*)(out + (size_t)(n0 + r) * 16 + cb) = make_float4(o[0], o[1], o[2], o[3]);
    }
}

// =====================================================================
extern "C" void kernel_launch(void* const* d_in, const int* in_sizes, int n_in,
                              void* d_out, int out_size)
{
    const float* feat = (const float*)d_in[0];
    const int*   src  = (const int*)d_in[1];
    const int*   dst  = (const int*)d_in[2];
    const void*  et   = d_in[3];
    const float* W0   = (const float*)d_in[4];
    const float* b0   = (const float*)d_in[5];
    const float* W1   = (const float*)d_in[6];
    const float* b1   = (const float*)d_in[7];
    const float* Wih  = (const float*)d_in[8];
    const float* Whh  = (const float*)d_in[9];
    const float* bih  = (const float*)d_in[10];
    const float* bhh  = (const float*)d_in[11];
    const float* Wout = (const float*)d_in[12];
    const float* bout = (const float*)d_in[13];
    float* out = (float*)d_out;

    const int E  = in_sizes[1];
    const int Nn = in_sizes[0] / HDIM;

    void* p;
    cudaGetSymbolAddress(&p, g_cnt);
    cudaMemsetAsync(p, 0, sizeof(int) * 2 * N_NODES);

    detect_et_kernel<<<1, 256>>>((const unsigned char*)et, E);
    place_kernel<<<(E + 255) / 256, 256>>>(src, dst, et, E);
    compose_kernel<<<48, 256>>>(Wih, W0, W1, b0, b1);

    size_t smem = SMEM_FLOATS * sizeof(float);   // 194624 B
    cudaFuncSetAttribute(node_kernel, cudaFuncAttributeMaxDynamicSharedMemorySize, (int)smem);
    int nb = (Nn + NPB - 1) / NPB;
    node_kernel<<<nb, TPB, smem>>>(feat, Whh, Wout, bih, bhh, bout, out, Nn);
}

// round 16
// speedup vs baseline: 1.4190x; 1.0945x over previous
#include <cuda_runtime.h>
#include <math.h>

#define N_NODES 100000
#define HDIM 64
#define NPB  128
#define TPB  512
#define PAD  32
#define OVF_CAP 65536

// smem layout (float indices)
#define O_CNT 0        // 256
#define O_B   256      // 784  (u0|u1|bih|bhh|bout)
#define O_F   1040     // 128*68 feat tile
#define O_S0  9744     // 128*68 S0 (later h)
#define O_S1  18448    // 128*68 S1
#define O_W0  27152    // 192*68 weight buf 0 (n-major)
#define O_W1  40208    // 192*68 weight buf 1 (n-major) / classifier W
#define SMEM_FLOATS 53264
#define XS 68
#define WS 68

__device__ int   g_cnt[2 * N_NODES];
__device__ int   g_slots[(size_t)2 * N_NODES * PAD];
__device__ int   g_et_is_i32;
__device__ int   g_ovf_n;
__device__ int2  g_ovf[OVF_CAP];
__device__ float g_C0[192 * 64];
__device__ float g_C1[192 * 64];
__device__ float g_u0[192];
__device__ float g_u1[192];

__device__ __forceinline__ unsigned tf32c(float x)
{
    unsigned r; asm("cvt.rna.tf32.f32 %0, %1;" : "=r"(r) : "f"(x)); return r;
}
__device__ __forceinline__ float tanh_fast(float x)
{
    float t; asm("tanh.approx.f32 %0, %1;" : "=f"(t) : "f"(x)); return t;
}
__device__ __forceinline__ float sigmoid_fast(float x)
{
    return 0.5f * tanh_fast(0.5f * x) + 0.5f;
}
#define MMA(d, a0, a1, a2, a3, b0, b1) \
    asm volatile("mma.sync.aligned.m16n8k8.row.col.f32.tf32.tf32.f32 " \
        "{%0,%1,%2,%3},{%4,%5,%6,%7},{%8,%9},{%0,%1,%2,%3};" \
        : "+f"((d)[0]), "+f"((d)[1]), "+f"((d)[2]), "+f"((d)[3]) \
        : "r"(a0), "r"(a1), "r"(a2), "r"(a3), "r"(b0), "r"(b1))

// =====================================================================
__global__ void detect_et_kernel(const unsigned char* __restrict__ et, int E)
{
    __shared__ int cnt;
    if (threadIdx.x == 0) { cnt = 0; g_ovf_n = 0; }
    __syncthreads();
    int K = 4096 < E ? 4096 : E;
    int local = 0;
    for (int i = threadIdx.x; i < K; i += blockDim.x) local += (et[i] != 0);
    atomicAdd(&cnt, local);
    __syncthreads();
    if (threadIdx.x == 0) g_et_is_i32 = (cnt < K / 4) ? 1 : 0;
}

__global__ void __launch_bounds__(256) place_kernel(
    const int* __restrict__ src, const int* __restrict__ dst,
    const void* __restrict__ et, int E)
{
    int e = blockIdx.x * blockDim.x + threadIdx.x;
    if (e >= E) return;
    bool t;
    if (g_et_is_i32) t = __ldg((const int*)et + e) != 0;
    else             t = __ldg((const unsigned char*)et + e) != 0;
    int ti = t ? 0 : 1;
    int d = __ldg(dst + e), s = __ldg(src + e);
    int seg = d * 2 + ti;
    int slot = atomicAdd(&g_cnt[seg], 1);
    if (slot < PAD) g_slots[(size_t)seg * PAD + slot] = s;
    else {
        int w = atomicAdd(&g_ovf_n, 1);
        if (w < OVF_CAP) g_ovf[w] = make_int2(seg, s);
    }
}

// C0 = Wih@W0, C1 = Wih@W1, u0 = Wih@b0, u1 = Wih@b1
__global__ void compose_kernel(const float* __restrict__ Wih,
                               const float* __restrict__ W0, const float* __restrict__ W1,
                               const float* __restrict__ b0, const float* __restrict__ b1)
{
    int idx = blockIdx.x * blockDim.x + threadIdx.x;
    if (idx < 192 * 64) {
        int r = idx >> 6, k = idx & 63;
        const float* wr = Wih + r * 64;
        float a0 = 0.f, a1 = 0.f;
        #pragma unroll 8
        for (int j = 0; j < 64; j++) {
            float w = __ldg(wr + j);
            a0 += w * __ldg(W0 + j * 64 + k);
            a1 += w * __ldg(W1 + j * 64 + k);
        }
        g_C0[idx] = a0; g_C1[idx] = a1;
    }
    if (idx < 192) {
        const float* wr = Wih + idx * 64;
        float s0 = 0.f, s1 = 0.f;
        #pragma unroll 8
        for (int j = 0; j < 64; j++) {
            float w = __ldg(wr + j);
            s0 += w * __ldg(b0 + j);
            s1 += w * __ldg(b1 + j);
        }
        g_u0[idx] = s0; g_u1[idx] = s1;
    }
}

// =====================================================================
// n-major staging: sW[n*WS + k] = tf32(W[n][k]); pure float4 copy
__device__ __forceinline__ void stage_w192(float* sW, const float* __restrict__ W, int tid)
{
    #pragma unroll
    for (int ii = 0; ii < 6; ii++) {
        int i = tid + ii * TPB;          // 0..3071
        int n = i >> 4, k4 = i & 15;
        float4 v = __ldg((const float4*)W + i);
        *(uint4*)(sW + n * WS + k4 * 4) =
            make_uint4(tf32c(v.x), tf32c(v.y), tf32c(v.z), tf32c(v.w));
    }
}

// GEMM pass: D[48] += Xtile(16 rows at rA) @ W^T (this warp's 12 n-tiles)
__device__ __forceinline__ void gemm_pass(float* D, const float* sX, const float* sW,
                                          int rA, int tid4, int gid, int h)
{
    #pragma unroll
    for (int kt = 0; kt < 8; kt++) {
        const float* ax = sX + rA * XS + kt * 8 + tid4;
        unsigned a0 = __float_as_uint(ax[0]);
        unsigned a1 = __float_as_uint(ax[8 * XS]);
        unsigned a2 = __float_as_uint(ax[4]);
        unsigned a3 = __float_as_uint(ax[8 * XS + 4]);
        const float* bx = sW + (size_t)(gid + h * 32) * WS + kt * 8 + tid4;
        #pragma unroll
        for (int g = 0; g < 3; g++) {
            #pragma unroll
            for (int q = 0; q < 4; q++) {
                const float* bp = bx + (g * 64 + q * 8) * WS;
                unsigned b0 = __float_as_uint(bp[0]);
                unsigned b1 = __float_as_uint(bp[4]);
                MMA(D + (g * 4 + q) * 4, a0, a1, a2, a3, b0, b1);
            }
        }
    }
}

// feat pass: r,z gates -> D, n gate -> Dgn (kept separate for GRU)
__device__ __forceinline__ void gemm_feat(float* D, float* Dgn, const float* sX,
                                          const float* sW, int rA, int tid4, int gid, int h)
{
    #pragma unroll
    for (int kt = 0; kt < 8; kt++) {
        const float* ax = sX + rA * XS + kt * 8 + tid4;
        unsigned a0 = __float_as_uint(ax[0]);
        unsigned a1 = __float_as_uint(ax[8 * XS]);
        unsigned a2 = __float_as_uint(ax[4]);
        unsigned a3 = __float_as_uint(ax[8 * XS + 4]);
        const float* bx = sW + (size_t)(gid + h * 32) * WS + kt * 8 + tid4;
        #pragma unroll
        for (int g = 0; g < 2; g++) {
            #pragma unroll
            for (int q = 0; q < 4; q++) {
                const float* bp = bx + (g * 64 + q * 8) * WS;
                unsigned b0 = __float_as_uint(bp[0]);
                unsigned b1 = __float_as_uint(bp[4]);
                MMA(D + (g * 4 + q) * 4, a0, a1, a2, a3, b0, b1);
            }
        }
        #pragma unroll
        for (int q = 0; q < 4; q++) {
            const float* bp = bx + (128 + q * 8) * WS;
            unsigned b0 = __float_as_uint(bp[0]);
            unsigned b1 = __float_as_uint(bp[4]);
            MMA(Dgn + q * 4, a0, a1, a2, a3, b0, b1);
        }
    }
}

__global__ void __launch_bounds__(TPB, 1) node_kernel(
    const float* __restrict__ feat,
    const float* __restrict__ Whh, const float* __restrict__ Wout,
    const float* __restrict__ bih, const float* __restrict__ bhh,
    const float* __restrict__ bout,
    float* __restrict__ out, int Nn)
{
    extern __shared__ __align__(16) float sm[];
    float* sCnt = sm + O_CNT;
    float* sB   = sm + O_B;
    float* sF   = sm + O_F;
    float* sS0  = sm + O_S0;
    float* sS1  = sm + O_S1;
    float* sW0  = sm + O_W0;
    float* sW1  = sm + O_W1;

    const int tid  = threadIdx.x;
    const int wid  = tid >> 5;
    const int lane = tid & 31;
    const int gid  = lane >> 2;
    const int tid4 = lane & 3;
    const int pair = wid >> 1;
    const int h    = wid & 1;
    const int rA   = pair * 16 + gid;
    const int n0   = blockIdx.x * NPB;
    const float4* F = (const float4*)feat;

    for (int i = tid; i < 784; i += TPB) {
        float v;
        if (i < 192)      v = g_u0[i];
        else if (i < 384) v = g_u1[i - 192];
        else if (i < 576) v = __ldg(bih + i - 384);
        else if (i < 768) v = __ldg(bhh + i - 576);
        else              v = __ldg(bout + i - 768);
        sB[i] = v;
    }
    for (int i = tid; i < 256; i += TPB) {
        int m = i & 127, t = i >> 7;
        int nn = n0 + m;
        sCnt[t * 128 + m] = (nn < Nn) ? (float)g_cnt[nn * 2 + t] : 0.f;
    }
    // feat tile (tf32)
    for (int i = tid; i < NPB * 16; i += TPB) {
        int r = i >> 4, l = i & 15;
        int nn = n0 + r;
        float4 v = (nn < Nn) ? __ldg(F + (size_t)nn * 16 + l) : make_float4(0.f, 0.f, 0.f, 0.f);
        *(uint4*)(sF + r * XS + l * 4) = make_uint4(tf32c(v.x), tf32c(v.y), tf32c(v.z), tf32c(v.w));
    }
    // gather S0 and S1 (fused)
    {
        int ovn = g_ovf_n; if (ovn > OVF_CAP) ovn = OVF_CAP;
        #pragma unroll 2
        for (int it = 0; it < 8; it++) {
            int i = tid + it * TPB;          // 0..4095
            int ti = i >> 11;
            int idx = i & 2047;
            int r = idx >> 4, l = idx & 15;
            int nn = n0 + r;
            float4 acc = make_float4(0.f, 0.f, 0.f, 0.f);
            if (nn < Nn) {
                int seg = nn * 2 + ti;
                int c = g_cnt[seg];
                int m = c < PAD ? c : PAD;
                const int* sl = g_slots + (size_t)seg * PAD;
                int q = 0;
                for (; q + 4 <= m; q += 4) {
                    int4 s4 = *(const int4*)(sl + q);
                    float4 a = __ldg(F + (size_t)s4.x * 16 + l);
                    float4 b = __ldg(F + (size_t)s4.y * 16 + l);
                    float4 c2 = __ldg(F + (size_t)s4.z * 16 + l);
                    float4 e = __ldg(F + (size_t)s4.w * 16 + l);
                    acc.x += (a.x + b.x) + (c2.x + e.x);
                    acc.y += (a.y + b.y) + (c2.y + e.y);
                    acc.z += (a.z + b.z) + (c2.z + e.z);
                    acc.w += (a.w + b.w) + (c2.w + e.w);
                }
                for (; q < m; q++) {
                    float4 a = __ldg(F + (size_t)sl[q] * 16 + l);
                    acc.x += a.x; acc.y += a.y; acc.z += a.z; acc.w += a.w;
                }
                for (int o = 0; o < ovn; o++) {
                    int2 ov = g_ovf[o];
                    if (ov.x == seg) {
                        float4 v = __ldg(F + (size_t)ov.y * 16 + l);
                        acc.x += v.x; acc.y += v.y; acc.z += v.z; acc.w += v.w;
                    }
                }
            }
            float* dstX = ti ? sS1 : sS0;
            *(uint4*)(dstX + r * XS + l * 4) =
                make_uint4(tf32c(acc.x), tf32c(acc.y), tf32c(acc.z), tf32c(acc.w));
        }
    }
    stage_w192(sW0, g_C0, tid);
    __syncthreads();

    // ---- phase 1: stage C1->W1 (overlaps) ; D = S0 @ C0^T ----
    float D[48];
    #pragma unroll
    for (int q = 0; q < 48; q++) D[q] = 0.f;
    stage_w192(sW1, g_C1, tid);
    gemm_pass(D, sS0, sW0, rA, tid4, gid, h);
    __syncthreads();

    // ---- phase 2: stage Whh->W0 (overlaps) ; D += S1 @ C1^T ----
    stage_w192(sW0, Whh, tid);
    gemm_pass(D, sS1, sW1, rA, tid4, gid, h);
    __syncthreads();

    // ---- phase 3: stage Wout->W1 ; D_rz += feat@Whh_rz^T, Dgn = feat@Whh_n^T ----
    for (int i = tid; i < 1024; i += TPB) {
        int c = i >> 6, k = i & 63;
        sW1[k * 16 + c] = __ldg(Wout + i);
    }
    float Dgn[16];
    #pragma unroll
    for (int q = 0; q < 16; q++) Dgn[q] = 0.f;
    gemm_feat(D, Dgn, sF, sW0, rA, tid4, gid, h);

    // ---- elementwise GRU (fp32); h -> sS0 (dead since phase 1) ----
    #pragma unroll
    for (int j = 0; j < 2; j++) {
        const int row = rA + j * 8;
        const float c0m = sCnt[row], c1m = sCnt[128 + row];
        const int valid = (n0 + row) < Nn;
        #pragma unroll
        for (int q = 0; q < 4; q++) {
            float2 fv = make_float2(0.f, 0.f);
            int c = h * 32 + q * 8 + tid4 * 2;
            if (valid)
                fv = *(const float2*)(feat + (size_t)(n0 + row) * 64 + c);
            #pragma unroll
            for (int e = 0; e < 2; e++) {
                int cc = c + e;
                float gr = D[q * 4 + j * 2 + e]       + c0m * sB[cc]       + c1m * sB[192 + cc]
                         + sB[384 + cc] + sB[576 + cc];
                float gz = D[(4 + q) * 4 + j * 2 + e] + c0m * sB[64 + cc]  + c1m * sB[256 + cc]
                         + sB[448 + cc] + sB[640 + cc];
                float gn = D[(8 + q) * 4 + j * 2 + e] + c0m * sB[128 + cc] + c1m * sB[320 + cc]
                         + sB[512 + cc];
                float hn = Dgn[q * 4 + j * 2 + e] + sB[704 + cc];
                float rr = sigmoid_fast(gr);
                float zz = sigmoid_fast(gz);
                float nn = tanh_fast(gn + rr * hn);
                float f  = (e == 0) ? fv.x : fv.y;
                sS0[row * XS + cc] = nn + zz * (f - nn);
            }
        }
    }
    __syncthreads();

    // ---- classifier (scalar fp32): out = h @ Wout^T + bout ----
    {
        int r  = tid >> 2;
        int cb = (tid & 3) * 4;
        float o[4];
        #pragma unroll
        for (int c = 0; c < 4; c++) o[c] = sB[768 + cb + c];
        #pragma unroll 4
        for (int k = 0; k < 64; k++) {
            float hv = sS0[r * XS + k];
            float4 w0 = *(const float4*)(sW1 + k * 16 + cb);
            o[0] += hv * w0.x; o[1] += hv * w0.y; o[2] += hv * w0.z; o[3] += hv * w0.w;
        }
        if (n0 + r < Nn)
            *(float4*)(out + (size_t)(n0 + r) * 16 + cb) = make_float4(o[0], o[1], o[2], o[3]);
    }
}

// =====================================================================
extern "C" void kernel_launch(void* const* d_in, const int* in_sizes, int n_in,
                              void* d_out, int out_size)
{
    const float* feat = (const float*)d_in[0];
    const int*   src  = (const int*)d_in[1];
    const int*   dst  = (const int*)d_in[2];
    const void*  et   = d_in[3];
    const float* W0   = (const float*)d_in[4];
    const float* b0   = (const float*)d_in[5];
    const float* W1   = (const float*)d_in[6];
    const float* b1   = (const float*)d_in[7];
    const float* Wih  = (const float*)d_in[8];
    const float* Whh  = (const float*)d_in[9];
    const float* bih  = (const float*)d_in[10];
    const float* bhh  = (const float*)d_in[11];
    const float* Wout = (const float*)d_in[12];
    const float* bout = (const float*)d_in[13];
    float* out = (float*)d_out;

    const int E  = in_sizes[1];
    const int Nn = in_sizes[0] / HDIM;

    void* p;
    cudaGetSymbolAddress(&p, g_cnt);
    cudaMemsetAsync(p, 0, sizeof(int) * 2 * N_NODES);

    detect_et_kernel<<<1, 256>>>((const unsigned char*)et, E);
    place_kernel<<<(E + 255) / 256, 256>>>(src, dst, et, E);
    compose_kernel<<<48, 256>>>(Wih, W0, W1, b0, b1);

    size_t smem = SMEM_FLOATS * sizeof(float);   // 213056 B
    cudaFuncSetAttribute(node_kernel, cudaFuncAttributeMaxDynamicSharedMemorySize, (int)smem);
    int nb = (Nn + NPB - 1) / NPB;
    node_kernel<<<nb, TPB, smem>>>(feat, Whh, Wout, bih, bhh, bout, out, Nn);
}

// round 17
// speedup vs baseline: 1.6992x; 1.1975x over previous
#include <cuda_runtime.h>
#include <cuda_fp16.h>
#include <math.h>

#define N_NODES 100000
#define HDIM 64
#define NPB  128
#define TPB  512
#define PAD  32
#define OVF_CAP 65536

// smem layout (bytes)
#define OB_CNT 0        // float[256]
#define OB_B   1024     // float[784]
#define OB_X0  4160     // half 128x72 (feat, later S1)
#define OB_X1  22592    // half 128x72 (S0, later h)
#define OB_W0  41024    // half 192x72
#define OB_W1  68672    // half 192x72 (later Wout fp32)
#define SMEM_BYTES 96320
#define XS2 72
#define WS2 72

__device__ int   g_cnt[2 * N_NODES];
__device__ int   g_slots[(size_t)2 * N_NODES * PAD];
__device__ int   g_et_is_i32;
__device__ int   g_ovf_n;
__device__ int2  g_ovf[OVF_CAP];
__device__ float g_C0[192 * 64];
__device__ float g_C1[192 * 64];
__device__ float g_u0[192];
__device__ float g_u1[192];

__device__ __forceinline__ float tanh_fast(float x)
{
    float t; asm("tanh.approx.f32 %0, %1;" : "=f"(t) : "f"(x)); return t;
}
__device__ __forceinline__ float sigmoid_fast(float x)
{
    return 0.5f * tanh_fast(0.5f * x) + 0.5f;
}
__device__ __forceinline__ unsigned h2u(float a, float b)
{
    __half2 h = __floats2half2_rn(a, b);
    return *(unsigned*)&h;
}
#define MMA16(d, a0, a1, a2, a3, b0, b1) \
    asm volatile("mma.sync.aligned.m16n8k16.row.col.f32.f16.f16.f32 " \
        "{%0,%1,%2,%3},{%4,%5,%6,%7},{%8,%9},{%0,%1,%2,%3};" \
        : "+f"((d)[0]), "+f"((d)[1]), "+f"((d)[2]), "+f"((d)[3]) \
        : "r"(a0), "r"(a1), "r"(a2), "r"(a3), "r"(b0), "r"(b1))

// =====================================================================
__global__ void detect_et_kernel(const unsigned char* __restrict__ et, int E)
{
    __shared__ int cnt;
    if (threadIdx.x == 0) { cnt = 0; g_ovf_n = 0; }
    __syncthreads();
    int K = 4096 < E ? 4096 : E;
    int local = 0;
    for (int i = threadIdx.x; i < K; i += blockDim.x) local += (et[i] != 0);
    atomicAdd(&cnt, local);
    __syncthreads();
    if (threadIdx.x == 0) g_et_is_i32 = (cnt < K / 4) ? 1 : 0;
}

__global__ void __launch_bounds__(256) place_kernel(
    const int* __restrict__ src, const int* __restrict__ dst,
    const void* __restrict__ et, int E)
{
    int e = blockIdx.x * blockDim.x + threadIdx.x;
    if (e >= E) return;
    bool t;
    if (g_et_is_i32) t = __ldg((const int*)et + e) != 0;
    else             t = __ldg((const unsigned char*)et + e) != 0;
    int ti = t ? 0 : 1;
    int d = __ldg(dst + e), s = __ldg(src + e);
    int seg = d * 2 + ti;
    int slot = atomicAdd(&g_cnt[seg], 1);
    if (slot < PAD) g_slots[(size_t)seg * PAD + slot] = s;
    else {
        int w = atomicAdd(&g_ovf_n, 1);
        if (w < OVF_CAP) g_ovf[w] = make_int2(seg, s);
    }
}

// C0 = Wih@W0, C1 = Wih@W1, u0 = Wih@b0, u1 = Wih@b1
__global__ void compose_kernel(const float* __restrict__ Wih,
                               const float* __restrict__ W0, const float* __restrict__ W1,
                               const float* __restrict__ b0, const float* __restrict__ b1)
{
    int idx = blockIdx.x * blockDim.x + threadIdx.x;
    if (idx < 192 * 64) {
        int r = idx >> 6, k = idx & 63;
        const float* wr = Wih + r * 64;
        float a0 = 0.f, a1 = 0.f;
        #pragma unroll 8
        for (int j = 0; j < 64; j++) {
            float w = __ldg(wr + j);
            a0 += w * __ldg(W0 + j * 64 + k);
            a1 += w * __ldg(W1 + j * 64 + k);
        }
        g_C0[idx] = a0; g_C1[idx] = a1;
    }
    if (idx < 192) {
        const float* wr = Wih + idx * 64;
        float s0 = 0.f, s1 = 0.f;
        #pragma unroll 8
        for (int j = 0; j < 64; j++) {
            float w = __ldg(wr + j);
            s0 += w * __ldg(b0 + j);
            s1 += w * __ldg(b1 + j);
        }
        g_u0[idx] = s0; g_u1[idx] = s1;
    }
}

// =====================================================================
// n-major half staging: sW[n*WS2 + k] = half(W[n][k]); float4 -> uint2
__device__ __forceinline__ void stage_w192h(__half* sW, const float* __restrict__ W, int tid)
{
    #pragma unroll
    for (int ii = 0; ii < 6; ii++) {
        int i = tid + ii * TPB;          // 0..3071
        int n = i >> 4, k4 = i & 15;
        float4 v = __ldg((const float4*)W + i);
        *(uint2*)(sW + n * WS2 + k4 * 4) = make_uint2(h2u(v.x, v.y), h2u(v.z, v.w));
    }
}

// gather one type's segment sums into half tile
__device__ __forceinline__ void gather_seg_h(__half* dstX, const float4* __restrict__ F,
                                             int n0, int ti, int Nn, int tid)
{
    int ovn = g_ovf_n; if (ovn > OVF_CAP) ovn = OVF_CAP;
    #pragma unroll 2
    for (int it = 0; it < 4; it++) {
        int idx = tid + it * TPB;        // 0..2047
        int r = idx >> 4, l = idx & 15;
        int nn = n0 + r;
        float4 acc = make_float4(0.f, 0.f, 0.f, 0.f);
        if (nn < Nn) {
            int seg = nn * 2 + ti;
            int c = g_cnt[seg];
            int m = c < PAD ? c : PAD;
            const int* sl = g_slots + (size_t)seg * PAD;
            int q = 0;
            for (; q + 4 <= m; q += 4) {
                int4 s4 = *(const int4*)(sl + q);
                float4 a = __ldg(F + (size_t)s4.x * 16 + l);
                float4 b = __ldg(F + (size_t)s4.y * 16 + l);
                float4 c2 = __ldg(F + (size_t)s4.z * 16 + l);
                float4 e = __ldg(F + (size_t)s4.w * 16 + l);
                acc.x += (a.x + b.x) + (c2.x + e.x);
                acc.y += (a.y + b.y) + (c2.y + e.y);
                acc.z += (a.z + b.z) + (c2.z + e.z);
                acc.w += (a.w + b.w) + (c2.w + e.w);
            }
            for (; q < m; q++) {
                float4 a = __ldg(F + (size_t)sl[q] * 16 + l);
                acc.x += a.x; acc.y += a.y; acc.z += a.z; acc.w += a.w;
            }
            for (int o = 0; o < ovn; o++) {
                int2 ov = g_ovf[o];
                if (ov.x == seg) {
                    float4 v = __ldg(F + (size_t)ov.y * 16 + l);
                    acc.x += v.x; acc.y += v.y; acc.z += v.z; acc.w += v.w;
                }
            }
        }
        *(uint2*)(dstX + r * XS2 + l * 4) = make_uint2(h2u(acc.x, acc.y), h2u(acc.z, acc.w));
    }
}

// GEMM pass: D[48] += Xtile(16 rows at rA) @ W^T (this warp's 12 n-tiles)
__device__ __forceinline__ void gemm_pass_h(float* D, const __half* X, const __half* W,
                                            int rA, int tid4, int gid, int h)
{
    #pragma unroll
    for (int kt = 0; kt < 4; kt++) {
        const __half* ax = X + rA * XS2 + kt * 16;
        unsigned a0 = *(const unsigned*)(ax + 2 * tid4);
        unsigned a1 = *(const unsigned*)(ax + 8 * XS2 + 2 * tid4);
        unsigned a2 = *(const unsigned*)(ax + 2 * tid4 + 8);
        unsigned a3 = *(const unsigned*)(ax + 8 * XS2 + 2 * tid4 + 8);
        const __half* bx = W + (size_t)(gid + h * 32) * WS2 + kt * 16 + 2 * tid4;
        #pragma unroll
        for (int g = 0; g < 3; g++) {
            #pragma unroll
            for (int q = 0; q < 4; q++) {
                const __half* bp = bx + (g * 64 + q * 8) * WS2;
                unsigned b0 = *(const unsigned*)bp;
                unsigned b1 = *(const unsigned*)(bp + 8);
                MMA16(D + (g * 4 + q) * 4, a0, a1, a2, a3, b0, b1);
            }
        }
    }
}

// feat pass: r,z -> D, n -> Dgn
__device__ __forceinline__ void gemm_feat_h(float* D, float* Dgn, const __half* X,
                                            const __half* W, int rA, int tid4, int gid, int h)
{
    #pragma unroll
    for (int kt = 0; kt < 4; kt++) {
        const __half* ax = X + rA * XS2 + kt * 16;
        unsigned a0 = *(const unsigned*)(ax + 2 * tid4);
        unsigned a1 = *(const unsigned*)(ax + 8 * XS2 + 2 * tid4);
        unsigned a2 = *(const unsigned*)(ax + 2 * tid4 + 8);
        unsigned a3 = *(const unsigned*)(ax + 8 * XS2 + 2 * tid4 + 8);
        const __half* bx = W + (size_t)(gid + h * 32) * WS2 + kt * 16 + 2 * tid4;
        #pragma unroll
        for (int g = 0; g < 2; g++) {
            #pragma unroll
            for (int q = 0; q < 4; q++) {
                const __half* bp = bx + (g * 64 + q * 8) * WS2;
                unsigned b0 = *(const unsigned*)bp;
                unsigned b1 = *(const unsigned*)(bp + 8);
                MMA16(D + (g * 4 + q) * 4, a0, a1, a2, a3, b0, b1);
            }
        }
        #pragma unroll
        for (int q = 0; q < 4; q++) {
            const __half* bp = bx + (128 + q * 8) * WS2;
            unsigned b0 = *(const unsigned*)bp;
            unsigned b1 = *(const unsigned*)(bp + 8);
            MMA16(Dgn + q * 4, a0, a1, a2, a3, b0, b1);
        }
    }
}

__global__ void __launch_bounds__(TPB, 1) node_kernel(
    const float* __restrict__ feat,
    const float* __restrict__ Whh, const float* __restrict__ Wout,
    const float* __restrict__ bih, const float* __restrict__ bhh,
    const float* __restrict__ bout,
    float* __restrict__ out, int Nn)
{
    extern __shared__ __align__(16) char smc[];
    float* sCnt = (float*)(smc + OB_CNT);
    float* sB   = (float*)(smc + OB_B);
    __half* X0  = (__half*)(smc + OB_X0);
    __half* X1  = (__half*)(smc + OB_X1);
    __half* W0h = (__half*)(smc + OB_W0);
    __half* W1h = (__half*)(smc + OB_W1);

    const int tid  = threadIdx.x;
    const int wid  = tid >> 5;
    const int lane = tid & 31;
    const int gid  = lane >> 2;
    const int tid4 = lane & 3;
    const int pair = wid >> 1;
    const int h    = wid & 1;
    const int rA   = pair * 16 + gid;
    const int n0   = blockIdx.x * NPB;
    const float4* F = (const float4*)feat;

    for (int i = tid; i < 784; i += TPB) {
        float v;
        if (i < 192)      v = g_u0[i];
        else if (i < 384) v = g_u1[i - 192];
        else if (i < 576) v = __ldg(bih + i - 384);
        else if (i < 768) v = __ldg(bhh + i - 576);
        else              v = __ldg(bout + i - 768);
        sB[i] = v;
    }
    for (int i = tid; i < 256; i += TPB) {
        int m = i & 127, t = i >> 7;
        int nn = n0 + m;
        sCnt[t * 128 + m] = (nn < Nn) ? (float)g_cnt[nn * 2 + t] : 0.f;
    }
    // feat tile -> X0 (half)
    #pragma unroll
    for (int ii = 0; ii < 4; ii++) {
        int i = tid + ii * TPB;
        int r = i >> 4, l = i & 15;
        int nn = n0 + r;
        float4 v = (nn < Nn) ? __ldg(F + (size_t)nn * 16 + l) : make_float4(0.f, 0.f, 0.f, 0.f);
        *(uint2*)(X0 + r * XS2 + l * 4) = make_uint2(h2u(v.x, v.y), h2u(v.z, v.w));
    }
    gather_seg_h(X1, F, n0, 0, Nn, tid);    // S0 -> X1
    stage_w192h(W0h, Whh, tid);
    __syncthreads();

    // ---- phase 1: stage C0->W1 ; D_rz/Dgn = feat @ Whh^T ----
    float D[48], Dgn[16];
    #pragma unroll
    for (int q = 0; q < 48; q++) D[q] = 0.f;
    #pragma unroll
    for (int q = 0; q < 16; q++) Dgn[q] = 0.f;
    stage_w192h(W1h, g_C0, tid);
    gemm_feat_h(D, Dgn, X0, W0h, rA, tid4, gid, h);
    __syncthreads();

    // ---- phase 2: gather S1->X0 (feat dead) ; stage C1->W0 ; D += S0 @ C0^T ----
    gather_seg_h(X0, F, n0, 1, Nn, tid);
    stage_w192h(W0h, g_C1, tid);
    gemm_pass_h(D, X1, W1h, rA, tid4, gid, h);
    __syncthreads();

    // ---- phase 3: stage Wout(fp32)->W1 region ; D += S1 @ C1^T ----
    float* sWo = (float*)W1h;
    for (int i = tid; i < 1024; i += TPB) {
        int c = i >> 6, k = i & 63;
        sWo[k * 16 + c] = __ldg(Wout + i);
    }
    gemm_pass_h(D, X0, W0h, rA, tid4, gid, h);

    // ---- elementwise GRU (fp32); h -> X1 as half (S0 dead after phase-2 sync) ----
    #pragma unroll
    for (int j = 0; j < 2; j++) {
        const int row = rA + j * 8;
        const float c0m = sCnt[row], c1m = sCnt[128 + row];
        const int valid = (n0 + row) < Nn;
        #pragma unroll
        for (int q = 0; q < 4; q++) {
            float2 fv = make_float2(0.f, 0.f);
            int c = h * 32 + q * 8 + tid4 * 2;
            if (valid)
                fv = *(const float2*)(feat + (size_t)(n0 + row) * 64 + c);
            float hv[2];
            #pragma unroll
            for (int e = 0; e < 2; e++) {
                int cc = c + e;
                float gr = D[q * 4 + j * 2 + e]       + c0m * sB[cc]       + c1m * sB[192 + cc]
                         + sB[384 + cc] + sB[576 + cc];
                float gz = D[(4 + q) * 4 + j * 2 + e] + c0m * sB[64 + cc]  + c1m * sB[256 + cc]
                         + sB[448 + cc] + sB[640 + cc];
                float gn = D[(8 + q) * 4 + j * 2 + e] + c0m * sB[128 + cc] + c1m * sB[320 + cc]
                         + sB[512 + cc];
                float hn = Dgn[q * 4 + j * 2 + e] + sB[704 + cc];
                float rr = sigmoid_fast(gr);
                float zz = sigmoid_fast(gz);
                float nn = tanh_fast(gn + rr * hn);
                float f  = (e == 0) ? fv.x : fv.y;
                hv[e] = nn + zz * (f - nn);
            }
            *(unsigned*)(X1 + row * XS2 + c) = h2u(hv[0], hv[1]);
        }
    }
    __syncthreads();

    // ---- classifier (fp32 from half h): out = h @ Wout^T + bout ----
    {
        int r  = tid >> 2;
        int cb = (tid & 3) * 4;
        float o[4];
        #pragma unroll
        for (int c = 0; c < 4; c++) o[c] = sB[768 + cb + c];
        #pragma unroll 4
        for (int k2 = 0; k2 < 32; k2++) {
            __half2 hp = *(const __half2*)(X1 + r * XS2 + k2 * 2);
            float2 hf = __half22float2(hp);
            float4 w0 = *(const float4*)(sWo + (k2 * 2) * 16 + cb);
            float4 w1 = *(const float4*)(sWo + (k2 * 2 + 1) * 16 + cb);
            o[0] += hf.x * w0.x + hf.y * w1.x;
            o[1] += hf.x * w0.y + hf.y * w1.y;
            o[2] += hf.x * w0.z + hf.y * w1.z;
            o[3] += hf.x * w0.w + hf.y * w1.w;
        }
        if (n0 + r < Nn)
            *(float4*)(out + (size_t)(n0 + r) * 16 + cb) = make_float4(o[0], o[1], o[2], o[3]);
    }
}

// =====================================================================
extern "C" void kernel_launch(void* const* d_in, const int* in_sizes, int n_in,
                              void* d_out, int out_size)
{
    const float* feat = (const float*)d_in[0];
    const int*   src  = (const int*)d_in[1];
    const int*   dst  = (const int*)d_in[2];
    const void*  et   = d_in[3];
    const float* W0   = (const float*)d_in[4];
    const float* b0   = (const float*)d_in[5];
    const float* W1   = (const float*)d_in[6];
    const float* b1   = (const float*)d_in[7];
    const float* Wih  = (const float*)d_in[8];
    const float* Whh  = (const float*)d_in[9];
    const float* bih  = (const float*)d_in[10];
    const float* bhh  = (const float*)d_in[11];
    const float* Wout = (const float*)d_in[12];
    const float* bout = (const float*)d_in[13];
    float* out = (float*)d_out;

    const int E  = in_sizes[1];
    const int Nn = in_sizes[0] / HDIM;

    void* p;
    cudaGetSymbolAddress(&p, g_cnt);
    cudaMemsetAsync(p, 0, sizeof(int) * 2 * N_NODES);

    detect_et_kernel<<<1, 256>>>((const unsigned char*)et, E);
    place_kernel<<<(E + 255) / 256, 256>>>(src, dst, et, E);
    compose_kernel<<<48, 256>>>(Wih, W0, W1, b0, b1);

    cudaFuncSetAttribute(node_kernel, cudaFuncAttributeMaxDynamicSharedMemorySize, SMEM_BYTES);
    int nb = (Nn + NPB - 1) / NPB;
    node_kernel<<<nb, TPB, SMEM_BYTES>>>(feat, Whh, Wout, bih, bhh, bout, out, Nn);
}